// round 3
// baseline (speedup 1.0000x reference)
#include <cuda_runtime.h>

#define BINS 10
#define TPB  256
#define GRID 912   // 152 SMs * 6 blocks: single wave even at ~40 regs/thread

// Global scratch (allocation-free: __device__ globals, zero-initialized at load;
// the last block re-zeros them each run so graph replays stay deterministic).
__device__ double       g_cnt[BINS];
__device__ double       g_sum[BINS];
__device__ unsigned int g_done;

__device__ __forceinline__ float rcp_fast(float x) { float r; asm("rcp.approx.f32 %0, %1;" : "=f"(r) : "f"(x)); return r; }
__device__ __forceinline__ float lg2_fast(float x) { float r; asm("lg2.approx.f32 %0, %1;" : "=f"(r) : "f"(x)); return r; }
__device__ __forceinline__ float ex2_fast(float x) { float r; asm("ex2.approx.f32 %0, %1;" : "=f"(r) : "f"(x)); return r; }

// Folded element: s = (y==1) ? -x : x, then
//   g   = sigmoid(s)  = (s>=0 ? 1 : e) / (1+e),  e = exp(-|s|)
//   bce = softplus(s) = max(s,0) + log1p(e)
// bin = floor(g * 9.9999) lands in [0,9] with no clamp (g <= 1.0 exactly).
__device__ __forceinline__ void ghm_elem(float s, float2* hcol)
{
    float e  = ex2_fast(fabsf(s) * -1.4426950408889634f);  // exp(-|s|): FMUL+MUFU
    float d  = 1.0f + e;
    float r  = rcp_fast(d);                                // MUFU.RCP
    float gn = (s >= 0.0f) ? 9.9999f : e * 9.9999f;        // numerator pre-scaled
    int bin  = (int)(gn * r);                              // FMUL + F2I
    float bce = fmaf(lg2_fast(d), 0.69314718055994531f, fmaxf(s, 0.0f));
    float2* p = hcol + bin * TPB;                          // bank = tid: conflict-free
    float2 h = *p;
    h.x += 1.0f;
    h.y += bce;
    *p = h;
}

__global__ void __launch_bounds__(TPB) ghm_fused(const float4* __restrict__ x4,
                                                 const int4*   __restrict__ t4,
                                                 int nquads, int nrows,
                                                 const float* __restrict__ xs,
                                                 const int*   __restrict__ ts,
                                                 float* __restrict__ out)
{
    __shared__ float2 hist[BINS][TPB];
    __shared__ int    s_last;
    const int tid = threadIdx.x;
    float2* hcol = &hist[0][tid];
#pragma unroll
    for (int b = 0; b < BINS; b++) hist[b][tid] = make_float2(0.0f, 0.0f);
    __syncthreads();

    const int stride = GRID * TPB;
    for (int i = blockIdx.x * TPB + tid; i < nquads; i += stride) {
        float4 xa = x4[2 * i];
        float4 xb = x4[2 * i + 1];
        int4   tv = t4[i];

        // Row sign masks: class1 mask = t<<31, class0 mask = that ^ signbit.
        unsigned ma1 = ((unsigned)tv.x) << 31, ma0 = ma1 ^ 0x80000000u;
        unsigned mb1 = ((unsigned)tv.y) << 31, mb0 = mb1 ^ 0x80000000u;
        unsigned mc1 = ((unsigned)tv.z) << 31, mc0 = mc1 ^ 0x80000000u;
        unsigned md1 = ((unsigned)tv.w) << 31, md0 = md1 ^ 0x80000000u;

        ghm_elem(__int_as_float(__float_as_int(xa.x) ^ ma0), hcol);
        ghm_elem(__int_as_float(__float_as_int(xa.y) ^ ma1), hcol);
        ghm_elem(__int_as_float(__float_as_int(xa.z) ^ mb0), hcol);
        ghm_elem(__int_as_float(__float_as_int(xa.w) ^ mb1), hcol);
        ghm_elem(__int_as_float(__float_as_int(xb.x) ^ mc0), hcol);
        ghm_elem(__int_as_float(__float_as_int(xb.y) ^ mc1), hcol);
        ghm_elem(__int_as_float(__float_as_int(xb.z) ^ md0), hcol);
        ghm_elem(__int_as_float(__float_as_int(xb.w) ^ md1), hcol);
    }

    // Tail rows (nrows % 4 != 0): direct double atomics, block 0 only.
    if (blockIdx.x == 0) {
        int tail0 = nquads * 4;
        for (int rowi = tail0 + tid; rowi < nrows; rowi += TPB) {
            int t = ts[rowi];
            for (int c = 0; c < 2; c++) {
                float x = xs[rowi * 2 + c];
                float s = (t == c) ? -x : x;
                float e = ex2_fast(fabsf(s) * -1.4426950408889634f);
                float d = 1.0f + e;
                float gn = (s >= 0.0f) ? 9.9999f : e * 9.9999f;
                int bin = (int)(gn * rcp_fast(d));
                float bce = fmaf(lg2_fast(d), 0.69314718055994531f, fmaxf(s, 0.0f));
                atomicAdd(&g_cnt[bin], 1.0);
                atomicAdd(&g_sum[bin], (double)bce);
            }
        }
    }
    __syncthreads();

    // Tree-reduce 256 columns x 10 bins.
    for (int off = TPB / 2; off > 0; off >>= 1) {
        if (tid < off) {
#pragma unroll
            for (int b = 0; b < BINS; b++) {
                float2 a = hist[b][tid];
                float2 c = hist[b][tid + off];
                hist[b][tid] = make_float2(a.x + c.x, a.y + c.y);
            }
        }
        __syncthreads();
    }

    if (tid < BINS) {
        atomicAdd(&g_cnt[tid], (double)hist[tid][0].x);
        atomicAdd(&g_sum[tid], (double)hist[tid][0].y);
    }
    __syncthreads();

    // Last-block finalize (and reset for the next graph replay).
    if (tid == 0) {
        __threadfence();
        unsigned old = atomicAdd(&g_done, 1u);
        s_last = (old == GRID - 1) ? 1 : 0;
    }
    __syncthreads();

    if (s_last && tid == 0) {
        __threadfence();
        volatile double* vc = g_cnt;
        volatile double* vs = g_sum;
        double cnt[BINS], sum[BINS];
        double nonempty = 0.0;
        for (int b = 0; b < BINS; b++) {
            cnt[b] = vc[b];
            sum[b] = vs[b];
            if (cnt[b] > 0.0) nonempty += 1.0;
        }
        // mean(weight*bce) = (1/N) * sum_b (N/gd_b) * S_b = sum_b S_b / gd_b
        double loss = 0.0;
        for (int b = 0; b < BINS; b++) {
            double gd = cnt[b] * nonempty;
            if (gd < 1e-4) gd = 1e-4;
            loss += sum[b] / gd;
        }
        out[0] = (float)loss;
        for (int b = 0; b < BINS; b++) { vc[b] = 0.0; vs[b] = 0.0; }
        __threadfence();
        g_done = 0u;
    }
}

extern "C" void kernel_launch(void* const* d_in, const int* in_sizes, int n_in,
                              void* d_out, int out_size)
{
    // x: [B,2] float32 (2B elems), target: [B] int32 (B elems) — identify by count.
    const float* x;
    const int*   t;
    int nrows;
    if (in_sizes[0] >= 2 * in_sizes[1]) {
        x = (const float*)d_in[0];
        t = (const int*)d_in[1];
        nrows = in_sizes[1];
    } else {
        x = (const float*)d_in[1];
        t = (const int*)d_in[0];
        nrows = in_sizes[0];
    }
    int nquads = nrows >> 2;

    ghm_fused<<<GRID, TPB>>>((const float4*)x, (const int4*)t, nquads, nrows,
                             x, t, (float*)d_out);
}

// round 4
// speedup vs baseline: 1.0117x; 1.0117x over previous
#include <cuda_runtime.h>

#define BINS 10
#define TPB  256
#define BPSM 5
#define GRID (152 * BPSM)   // exactly one wave on GB300 (152 SMs)

// Global scratch (allocation-free: __device__ globals, zero-initialized at load;
// the last block re-zeros them each run so graph replays stay deterministic).
__device__ double       g_cnt[BINS];
__device__ double       g_sum[BINS];
__device__ unsigned int g_done;

__device__ __forceinline__ float rcp_fast(float x) { float r; asm("rcp.approx.f32 %0, %1;" : "=f"(r) : "f"(x)); return r; }
__device__ __forceinline__ float lg2_fast(float x) { float r; asm("lg2.approx.f32 %0, %1;" : "=f"(r) : "f"(x)); return r; }
__device__ __forceinline__ float ex2_fast(float x) { float r; asm("ex2.approx.f32 %0, %1;" : "=f"(r) : "f"(x)); return r; }

// Folded element: s = (y==1) ? -x : x, then
//   g   = sigmoid(s)  = (s>=0 ? 1 : e) / (1+e),  e = exp(-|s|)
//   bce = softplus(s) = max(s,0) + log1p(e)
// bin = floor(g * 9.9999) lands in [0,9] with no clamp (g <= 1.0 exactly).
__device__ __forceinline__ void ghm_elem(float s, float2* hcol)
{
    float e  = ex2_fast(fabsf(s) * -1.4426950408889634f);  // exp(-|s|)
    float d  = 1.0f + e;
    float r  = rcp_fast(d);
    float gn = (s >= 0.0f) ? 9.9999f : e * 9.9999f;
    int bin  = (int)(gn * r);
    float bce = fmaf(lg2_fast(d), 0.69314718055994531f, fmaxf(s, 0.0f));
    float2* p = hcol + bin * TPB;   // bank = tid (mod 32): conflict-free
    float2 h = *p;
    h.x += 1.0f;
    h.y += bce;
    *p = h;
}

__global__ void __launch_bounds__(TPB, BPSM)
ghm_fused(const float4* __restrict__ x4,
          const int4*   __restrict__ t4,
          int nquads, int nrows,
          const float* __restrict__ xs,
          const int*   __restrict__ ts,
          float* __restrict__ out)
{
    // TWO privatized histograms (even/odd element slots) -> two independent
    // smem RMW chains per iteration instead of one 8-deep serialized chain.
    __shared__ float2 hist[2][BINS][TPB];
    __shared__ int    s_last;
    const int tid = threadIdx.x;
    float2* hc0 = &hist[0][0][tid];
    float2* hc1 = &hist[1][0][tid];
#pragma unroll
    for (int b = 0; b < BINS; b++) {
        hist[0][b][tid] = make_float2(0.0f, 0.0f);
        hist[1][b][tid] = make_float2(0.0f, 0.0f);
    }
    __syncthreads();

    const int stride = GRID * TPB;
    for (int i = blockIdx.x * TPB + tid; i < nquads; i += stride) {
        float4 xa = x4[2 * i];
        float4 xb = x4[2 * i + 1];
        int4   tv = t4[i];

        // Row sign masks: class1 mask = t<<31, class0 mask = that ^ signbit.
        unsigned ma1 = ((unsigned)tv.x) << 31, ma0 = ma1 ^ 0x80000000u;
        unsigned mb1 = ((unsigned)tv.y) << 31, mb0 = mb1 ^ 0x80000000u;
        unsigned mc1 = ((unsigned)tv.z) << 31, mc0 = mc1 ^ 0x80000000u;
        unsigned md1 = ((unsigned)tv.w) << 31, md0 = md1 ^ 0x80000000u;

        ghm_elem(__int_as_float(__float_as_int(xa.x) ^ ma0), hc0);
        ghm_elem(__int_as_float(__float_as_int(xa.y) ^ ma1), hc1);
        ghm_elem(__int_as_float(__float_as_int(xa.z) ^ mb0), hc0);
        ghm_elem(__int_as_float(__float_as_int(xa.w) ^ mb1), hc1);
        ghm_elem(__int_as_float(__float_as_int(xb.x) ^ mc0), hc0);
        ghm_elem(__int_as_float(__float_as_int(xb.y) ^ mc1), hc1);
        ghm_elem(__int_as_float(__float_as_int(xb.z) ^ md0), hc0);
        ghm_elem(__int_as_float(__float_as_int(xb.w) ^ md1), hc1);
    }

    // Tail rows (nrows % 4 != 0): direct double atomics, block 0 only.
    if (blockIdx.x == 0) {
        int tail0 = nquads * 4;
        for (int rowi = tail0 + tid; rowi < nrows; rowi += TPB) {
            int t = ts[rowi];
            for (int c = 0; c < 2; c++) {
                float x = xs[rowi * 2 + c];
                float s = (t == c) ? -x : x;
                float e = ex2_fast(fabsf(s) * -1.4426950408889634f);
                float d = 1.0f + e;
                float gn = (s >= 0.0f) ? 9.9999f : e * 9.9999f;
                int bin = (int)(gn * rcp_fast(d));
                float bce = fmaf(lg2_fast(d), 0.69314718055994531f, fmaxf(s, 0.0f));
                atomicAdd(&g_cnt[bin], 1.0);
                atomicAdd(&g_sum[bin], (double)bce);
            }
        }
    }
    __syncthreads();

    // Fold copy 1 into copy 0, then tree-reduce 256 columns x 10 bins.
#pragma unroll
    for (int b = 0; b < BINS; b++) {
        float2 a = hist[0][b][tid];
        float2 c = hist[1][b][tid];
        hist[0][b][tid] = make_float2(a.x + c.x, a.y + c.y);
    }
    __syncthreads();
    for (int off = TPB / 2; off > 0; off >>= 1) {
        if (tid < off) {
#pragma unroll
            for (int b = 0; b < BINS; b++) {
                float2 a = hist[0][b][tid];
                float2 c = hist[0][b][tid + off];
                hist[0][b][tid] = make_float2(a.x + c.x, a.y + c.y);
            }
        }
        __syncthreads();
    }

    if (tid < BINS) {
        atomicAdd(&g_cnt[tid], (double)hist[0][tid][0].x);
        atomicAdd(&g_sum[tid], (double)hist[0][tid][0].y);
    }
    __syncthreads();

    // Last-block finalize (and reset for the next graph replay).
    if (tid == 0) {
        __threadfence();
        unsigned old = atomicAdd(&g_done, 1u);
        s_last = (old == GRID - 1) ? 1 : 0;
    }
    __syncthreads();

    if (s_last && tid == 0) {
        __threadfence();
        volatile double* vc = g_cnt;
        volatile double* vs = g_sum;
        double cnt[BINS], sum[BINS];
        double nonempty = 0.0;
        for (int b = 0; b < BINS; b++) {
            cnt[b] = vc[b];
            sum[b] = vs[b];
            if (cnt[b] > 0.0) nonempty += 1.0;
        }
        // mean(weight*bce) = (1/N) * sum_b (N/gd_b) * S_b = sum_b S_b / gd_b
        double loss = 0.0;
        for (int b = 0; b < BINS; b++) {
            double gd = cnt[b] * nonempty;
            if (gd < 1e-4) gd = 1e-4;
            loss += sum[b] / gd;
        }
        out[0] = (float)loss;
        for (int b = 0; b < BINS; b++) { vc[b] = 0.0; vs[b] = 0.0; }
        __threadfence();
        g_done = 0u;
    }
}

extern "C" void kernel_launch(void* const* d_in, const int* in_sizes, int n_in,
                              void* d_out, int out_size)
{
    // x: [B,2] float32 (2B elems), target: [B] int32 (B elems) — identify by count.
    const float* x;
    const int*   t;
    int nrows;
    if (in_sizes[0] >= 2 * in_sizes[1]) {
        x = (const float*)d_in[0];
        t = (const int*)d_in[1];
        nrows = in_sizes[1];
    } else {
        x = (const float*)d_in[1];
        t = (const int*)d_in[0];
        nrows = in_sizes[0];
    }
    int nquads = nrows >> 2;

    ghm_fused<<<GRID, TPB>>>((const float4*)x, (const int4*)t, nquads, nrows,
                             x, t, (float*)d_out);
}